// round 4
// baseline (speedup 1.0000x reference)
#include <cuda_runtime.h>
#include <math.h>

// Problem constants
#define BB 256
#define PP 5
#define TT 256
#define FF 128
#define HH 512
#define CC 60
#define DD 640      // P*F
#define G4 2048     // 4*H

// Scratch state (device globals: allocation-free per harness rules)
__device__ float g_xw[134217728ULL];   // (T*B, 4H) = 65536 x 2048 fp32 (512 MB)
__device__ float g_h[2][BB * HH];      // double-buffered hidden state
__device__ float g_c[BB * HH];         // cell state

// ---------------------------------------------------------------------------
// Packed fp32x2 FMA (SASS FFMA2) — 2x fp32 FMA throughput on sm_103a
// ---------------------------------------------------------------------------
__device__ __forceinline__ float2 ffma2(float2 a, float2 b, float2 c) {
    unsigned long long ua = *reinterpret_cast<unsigned long long*>(&a);
    unsigned long long ub = *reinterpret_cast<unsigned long long*>(&b);
    unsigned long long uc = *reinterpret_cast<unsigned long long*>(&c);
    unsigned long long ud;
    asm("fma.rn.f32x2 %0, %1, %2, %3;" : "=l"(ud) : "l"(ua), "l"(ub), "l"(uc));
    return *reinterpret_cast<float2*>(&ud);
}

// ---------------------------------------------------------------------------
// Zero initial state
// ---------------------------------------------------------------------------
__global__ void zero_state() {
    int i = blockIdx.x * blockDim.x + threadIdx.x;
    if (i < BB * HH) {
        g_h[0][i] = 0.0f;
        g_c[i]    = 0.0f;
    }
}

// ---------------------------------------------------------------------------
// Phase 1: XW[t*B+b, :] = x_seq[t,b,:] @ Wx + bias
//   A[m,k] = inputs[b, p, t, f], m = t*256 + b, k = p*128 + f
//   M=65536, N=2048, K=640. Block tile 128x128, K-tile 16, double-buffered.
// ---------------------------------------------------------------------------
#define KT1 16
__global__ void __launch_bounds__(256, 2)
xw_gemm(const float* __restrict__ X, const float* __restrict__ Wx,
        const float* __restrict__ bvec) {
    __shared__ float a_s[2][KT1][130];   // [k][m], pad=130 -> conflict-free STS/LDS
    __shared__ float b_s[2][KT1][128];   // [k][n]

    const int tid = threadIdx.x;
    const int by  = blockIdx.y;          // 0..511 : m-tile
    const int n0  = blockIdx.x << 7;     // 0..15  : n-tile * 128
    const int t   = by >> 1;
    const int bb0 = (by & 1) << 7;

    const int tx = tid & 15;             // n group (stride-16 columns)
    const int ty = tid >> 4;             // m group (8 consecutive rows)

    // loader indices
    const int lakk = tid & 15;           // A: k within tile
    const int lamm = tid >> 4;           // A: m base (+16*i)
    const int lbnn = tid & 127;          // B: n
    const int lbk0 = (tid >> 7) << 3;    // B: k row base (0 or 8)

    float2 acc[8][4];
#pragma unroll
    for (int j = 0; j < 8; ++j)
#pragma unroll
        for (int p = 0; p < 4; ++p) acc[j][p] = make_float2(0.f, 0.f);

    float ra[8], rb[8];

    auto loadA = [&](int k0) {
        int p = k0 >> 7;
        int f = (k0 & 127) + lakk;
        size_t colofs = (size_t)p * (TT * FF) + (size_t)t * FF + f;
#pragma unroll
        for (int i = 0; i < 8; ++i)
            ra[i] = X[(size_t)(bb0 + lamm + 16 * i) * (PP * TT * FF) + colofs];
    };
    auto loadB = [&](int k0) {
#pragma unroll
        for (int i = 0; i < 8; ++i)
            rb[i] = Wx[(size_t)(k0 + lbk0 + i) * G4 + n0 + lbnn];
    };
    auto stsAB = [&](int buf) {
#pragma unroll
        for (int i = 0; i < 8; ++i) a_s[buf][lakk][lamm + 16 * i] = ra[i];
#pragma unroll
        for (int i = 0; i < 8; ++i) b_s[buf][lbk0 + i][lbnn] = rb[i];
    };

    const int NS = DD / KT1;   // 40 stages
    loadA(0); loadB(0);
    stsAB(0);
    __syncthreads();

    for (int s = 0; s < NS; ++s) {
        const int buf = s & 1;
        if (s + 1 < NS) { loadA((s + 1) * KT1); loadB((s + 1) * KT1); }
#pragma unroll
        for (int kk = 0; kk < KT1; ++kk) {
            float2 a01 = *(const float2*)&a_s[buf][kk][ty * 8 + 0];
            float2 a23 = *(const float2*)&a_s[buf][kk][ty * 8 + 2];
            float2 a45 = *(const float2*)&a_s[buf][kk][ty * 8 + 4];
            float2 a67 = *(const float2*)&a_s[buf][kk][ty * 8 + 6];
#pragma unroll
            for (int j = 0; j < 8; ++j) {
                float bv = b_s[buf][kk][tx + 16 * j];
                float2 bb = make_float2(bv, bv);
                acc[j][0] = ffma2(a01, bb, acc[j][0]);
                acc[j][1] = ffma2(a23, bb, acc[j][1]);
                acc[j][2] = ffma2(a45, bb, acc[j][2]);
                acc[j][3] = ffma2(a67, bb, acc[j][3]);
            }
        }
        if (s + 1 < NS) stsAB(buf ^ 1);
        __syncthreads();
    }

    // epilogue: add bias, store to g_xw
    const int mrow = by * 128 + ty * 8;
#pragma unroll
    for (int j = 0; j < 8; ++j) {
        int n = n0 + tx + 16 * j;
        float bn = bvec[n];
#pragma unroll
        for (int p = 0; p < 4; ++p) {
            size_t o = (size_t)(mrow + 2 * p) * G4 + n;
            g_xw[o]      = acc[j][p].x + bn;
            g_xw[o + G4] = acc[j][p].y + bn;
        }
    }
}

// ---------------------------------------------------------------------------
// Phase 2: one LSTM step (launched 256x).
//   gates = XW[t] + h_in @ Wh; fused gate nonlinearities + phased time gate.
//   Block = 32 batch x 32 channels (x 4 gates). Grid (8, 16).
// ---------------------------------------------------------------------------
#define KT2 32
__global__ void __launch_bounds__(256)
lstm_step(const float* __restrict__ Wh, const float* __restrict__ tau,
          const float* __restrict__ shift, int t) {
    __shared__ float a_s[2][KT2][34];    // h tile [k][m]
    __shared__ float b_s[2][KT2][128];   // Wh tile [k][gate*32+chan]

    const float* __restrict__ hin  = g_h[t & 1];
    float* __restrict__       hout = g_h[(t + 1) & 1];

    const int tid = threadIdx.x;
    const int m0  = blockIdx.x << 5;     // batch tile
    const int ch0 = blockIdx.y << 5;     // channel tile
    const int tn  = tid & 31;            // this thread's local channel
    const int tm  = tid >> 5;            // 0..7, 4 batch rows each

    // loader indices
    const int lakk = tid & 31;
    const int lamm = tid >> 5;
    const int lbn  = tid & 127;
    const int lbk0 = (tid >> 7) << 4;    // 0 or 16
    const int lbq  = lbn >> 5;
    const int lbcl = lbn & 31;
    const int wcol = lbq * HH + ch0 + lbcl;

    float2 acc[4][2];                    // [gate][m-pair]
#pragma unroll
    for (int q = 0; q < 4; ++q) { acc[q][0] = make_float2(0.f, 0.f); acc[q][1] = make_float2(0.f, 0.f); }

    float ra[4], rb[16];

    auto loadA = [&](int k0) {
#pragma unroll
        for (int i = 0; i < 4; ++i)
            ra[i] = hin[(size_t)(m0 + lamm + 8 * i) * HH + k0 + lakk];
    };
    auto loadB = [&](int k0) {
#pragma unroll
        for (int i = 0; i < 16; ++i)
            rb[i] = Wh[(size_t)(k0 + lbk0 + i) * G4 + wcol];
    };
    auto stsAB = [&](int buf) {
#pragma unroll
        for (int i = 0; i < 4; ++i) a_s[buf][lakk][lamm + 8 * i] = ra[i];
#pragma unroll
        for (int i = 0; i < 16; ++i) b_s[buf][lbk0 + i][lbn] = rb[i];
    };

    const int NS = HH / KT2;   // 16 stages
    loadA(0); loadB(0);
    stsAB(0);
    __syncthreads();

    for (int s = 0; s < NS; ++s) {
        const int buf = s & 1;
        if (s + 1 < NS) { loadA((s + 1) * KT2); loadB((s + 1) * KT2); }
#pragma unroll
        for (int kk = 0; kk < KT2; ++kk) {
            float2 a01 = *(const float2*)&a_s[buf][kk][tm * 4 + 0];
            float2 a23 = *(const float2*)&a_s[buf][kk][tm * 4 + 2];
#pragma unroll
            for (int q = 0; q < 4; ++q) {
                float bv = b_s[buf][kk][q * 32 + tn];
                float2 bb = make_float2(bv, bv);
                acc[q][0] = ffma2(a01, bb, acc[q][0]);
                acc[q][1] = ffma2(a23, bb, acc[q][1]);
            }
        }
        if (s + 1 < NS) stsAB(buf ^ 1);
        __syncthreads();
    }

    // fused epilogue: gate nonlinearities + phased time gate + state update
    const int ch = ch0 + tn;
    const float tv = tau[ch];
    const float sv = shift[ch];
    float xph = ((float)t - sv) / tv;
    float phi = xph - floorf(xph);
    float kg = (phi < 0.025f) ? (40.0f * phi)
             : (phi < 0.05f)  ? (2.0f - 40.0f * phi)
                              : (0.001f * phi);

    const size_t xwbase = (size_t)t * BB * G4;
#pragma unroll
    for (int p = 0; p < 2; ++p) {
#pragma unroll
        for (int r = 0; r < 2; ++r) {
            int m = m0 + tm * 4 + 2 * p + r;
            size_t xo = xwbase + (size_t)m * G4 + ch;
            float gi = (r ? acc[0][p].y : acc[0][p].x) + g_xw[xo];
            float gf = (r ? acc[1][p].y : acc[1][p].x) + g_xw[xo + 512];
            float gg = (r ? acc[2][p].y : acc[2][p].x) + g_xw[xo + 1024];
            float go = (r ? acc[3][p].y : acc[3][p].x) + g_xw[xo + 1536];
            gi = 1.0f / (1.0f + __expf(-gi));
            gf = 1.0f / (1.0f + __expf(-gf));
            gg = tanhf(gg);
            go = 1.0f / (1.0f + __expf(-go));
            size_t so = (size_t)m * HH + ch;
            float cold = g_c[so];
            float ct = gf * cold + gi * gg;
            float ht = go * tanhf(ct);
            float hold = hin[so];
            g_c[so]  = kg * ct + (1.0f - kg) * cold;
            hout[so] = kg * ht + (1.0f - kg) * hold;
        }
    }
}

// ---------------------------------------------------------------------------
// Phase 3: logits = hT @ fc_w + fc_b; log_softmax over C=60.
// One block per batch row. Final h lives in g_h[0] (T=256 is even).
// ---------------------------------------------------------------------------
__global__ void head_kernel(const float* __restrict__ fc_w,
                            const float* __restrict__ fc_b,
                            float* __restrict__ out) {
    __shared__ float hrow[HH];
    __shared__ float logits[CC];
    __shared__ float s_lse;
    const int b = blockIdx.x;
    const int tid = threadIdx.x;   // 64 threads

    for (int i = tid; i < HH; i += 64) hrow[i] = g_h[0][(size_t)b * HH + i];
    __syncthreads();

    if (tid < CC) {
        float s = fc_b[tid];
#pragma unroll 8
        for (int k = 0; k < HH; ++k) s += hrow[k] * fc_w[(size_t)k * CC + tid];
        logits[tid] = s;
    }
    __syncthreads();

    if (tid == 0) {
        float mx = -1e30f;
        for (int i = 0; i < CC; ++i) mx = fmaxf(mx, logits[i]);
        float sm = 0.0f;
        for (int i = 0; i < CC; ++i) sm += expf(logits[i] - mx);
        s_lse = mx + logf(sm);
    }
    __syncthreads();

    if (tid < CC) out[(size_t)b * CC + tid] = logits[tid] - s_lse;
}

// ---------------------------------------------------------------------------
// Launch: zero state -> XW precompute GEMM -> 256 step kernels -> head.
// All launches on the default stream; fully graph-capturable, no allocs.
// ---------------------------------------------------------------------------
extern "C" void kernel_launch(void* const* d_in, const int* in_sizes, int n_in,
                              void* d_out, int out_size) {
    const float* x     = (const float*)d_in[0];
    const float* Wx    = (const float*)d_in[1];
    const float* Wh    = (const float*)d_in[2];
    const float* bias  = (const float*)d_in[3];
    const float* tau   = (const float*)d_in[4];
    const float* shift = (const float*)d_in[5];
    const float* fc_w  = (const float*)d_in[6];
    const float* fc_b  = (const float*)d_in[7];
    float* out = (float*)d_out;

    zero_state<<<(BB * HH + 255) / 256, 256>>>();

    dim3 g1(G4 / 128, (TT * BB) / 128);   // (16, 512)
    xw_gemm<<<g1, 256>>>(x, Wx, bias);

    dim3 g2(BB / 32, HH / 32);            // (8, 16)
    for (int t = 0; t < TT; ++t)
        lstm_step<<<g2, 256>>>(Wh, tau, shift, t);

    head_kernel<<<BB, 64>>>(fc_w, fc_b, out);
}

// round 5
// speedup vs baseline: 1.0357x; 1.0357x over previous
#include <cuda_runtime.h>
#include <math.h>

// Problem constants
#define BB 256
#define PP 5
#define TT 256
#define FF 128
#define HH 512
#define CC 60
#define DD 640      // P*F
#define G4 2048     // 4*H

// Scratch state (device globals: allocation-free per harness rules)
__device__ float g_xw[134217728ULL];   // (T*B, 4H) = 65536 x 2048 fp32
__device__ float g_h[2][BB * HH];      // double-buffered hidden state
__device__ float g_c[BB * HH];         // cell state

// ---------------------------------------------------------------------------
// Packed fp32x2 FMA (SASS FFMA2) — 2x fp32 FMA throughput on sm_103a
// ---------------------------------------------------------------------------
__device__ __forceinline__ float2 ffma2(float2 a, float2 b, float2 c) {
    unsigned long long ua = *reinterpret_cast<unsigned long long*>(&a);
    unsigned long long ub = *reinterpret_cast<unsigned long long*>(&b);
    unsigned long long uc = *reinterpret_cast<unsigned long long*>(&c);
    unsigned long long ud;
    asm("fma.rn.f32x2 %0, %1, %2, %3;" : "=l"(ud) : "l"(ua), "l"(ub), "l"(uc));
    return *reinterpret_cast<float2*>(&ud);
}

// ---------------------------------------------------------------------------
// Zero initial state
// ---------------------------------------------------------------------------
__global__ void zero_state() {
    int i = blockIdx.x * blockDim.x + threadIdx.x;
    if (i < BB * HH) {
        g_h[0][i] = 0.0f;
        g_c[i]    = 0.0f;
    }
}

// ---------------------------------------------------------------------------
// Phase 1: XW[t*B+b, :] = x_seq[t,b,:] @ Wx + bias  (unchanged from R4)
// ---------------------------------------------------------------------------
#define KT1 16
__global__ void __launch_bounds__(256, 2)
xw_gemm(const float* __restrict__ X, const float* __restrict__ Wx,
        const float* __restrict__ bvec) {
    __shared__ float a_s[2][KT1][130];
    __shared__ float b_s[2][KT1][128];

    const int tid = threadIdx.x;
    const int by  = blockIdx.y;
    const int n0  = blockIdx.x << 7;
    const int t   = by >> 1;
    const int bb0 = (by & 1) << 7;

    const int tx = tid & 15;
    const int ty = tid >> 4;

    const int lakk = tid & 15;
    const int lamm = tid >> 4;
    const int lbnn = tid & 127;
    const int lbk0 = (tid >> 7) << 3;

    float2 acc[8][4];
#pragma unroll
    for (int j = 0; j < 8; ++j)
#pragma unroll
        for (int p = 0; p < 4; ++p) acc[j][p] = make_float2(0.f, 0.f);

    float ra[8], rb[8];

    auto loadA = [&](int k0) {
        int p = k0 >> 7;
        int f = (k0 & 127) + lakk;
        size_t colofs = (size_t)p * (TT * FF) + (size_t)t * FF + f;
#pragma unroll
        for (int i = 0; i < 8; ++i)
            ra[i] = X[(size_t)(bb0 + lamm + 16 * i) * (PP * TT * FF) + colofs];
    };
    auto loadB = [&](int k0) {
#pragma unroll
        for (int i = 0; i < 8; ++i)
            rb[i] = Wx[(size_t)(k0 + lbk0 + i) * G4 + n0 + lbnn];
    };
    auto stsAB = [&](int buf) {
#pragma unroll
        for (int i = 0; i < 8; ++i) a_s[buf][lakk][lamm + 16 * i] = ra[i];
#pragma unroll
        for (int i = 0; i < 8; ++i) b_s[buf][lbk0 + i][lbnn] = rb[i];
    };

    const int NS = DD / KT1;
    loadA(0); loadB(0);
    stsAB(0);
    __syncthreads();

    for (int s = 0; s < NS; ++s) {
        const int buf = s & 1;
        if (s + 1 < NS) { loadA((s + 1) * KT1); loadB((s + 1) * KT1); }
#pragma unroll
        for (int kk = 0; kk < KT1; ++kk) {
            float2 a01 = *(const float2*)&a_s[buf][kk][ty * 8 + 0];
            float2 a23 = *(const float2*)&a_s[buf][kk][ty * 8 + 2];
            float2 a45 = *(const float2*)&a_s[buf][kk][ty * 8 + 4];
            float2 a67 = *(const float2*)&a_s[buf][kk][ty * 8 + 6];
#pragma unroll
            for (int j = 0; j < 8; ++j) {
                float bv = b_s[buf][kk][tx + 16 * j];
                float2 bb = make_float2(bv, bv);
                acc[j][0] = ffma2(a01, bb, acc[j][0]);
                acc[j][1] = ffma2(a23, bb, acc[j][1]);
                acc[j][2] = ffma2(a45, bb, acc[j][2]);
                acc[j][3] = ffma2(a67, bb, acc[j][3]);
            }
        }
        if (s + 1 < NS) stsAB(buf ^ 1);
        __syncthreads();
    }

    const int mrow = by * 128 + ty * 8;
#pragma unroll
    for (int j = 0; j < 8; ++j) {
        int n = n0 + tx + 16 * j;
        float bn = bvec[n];
#pragma unroll
        for (int p = 0; p < 4; ++p) {
            size_t o = (size_t)(mrow + 2 * p) * G4 + n;
            g_xw[o]      = acc[j][p].x + bn;
            g_xw[o + G4] = acc[j][p].y + bn;
        }
    }
}

// ---------------------------------------------------------------------------
// Phase 2 (REWRITTEN): one LSTM step.
//   Block = 32 batch x 32 channels (x4 gates). Grid (8, 16) = 128 blocks.
//   Warp layout: lanes = 16 channels x 2 m-groups  -> b-tile LDS dedupes 2x.
//   a-tile stored [k][m] (loader transposes) -> LDS.128 gives 2 natural
//     batch-pair float2 operands for FFMA2.
//   b-tile stored gate-interleaved [k][ch][gate] (loader 4x4 reg-transpose)
//     -> one LDS.128 fetches all 4 gate weights.
//   Inner loop: 2 LDS.128 + 4 dup-MOV + 8 FFMA2 per kk  => fma-pipe bound.
// ---------------------------------------------------------------------------
#define KT2 32
#define APITCH 36
#define BPITCH 140
__global__ void __launch_bounds__(256, 1)
lstm_step(const float* __restrict__ Wh, const float* __restrict__ tau,
          const float* __restrict__ shift, int t) {
    __shared__ float a_s[2][KT2][APITCH];   // [k][m] transposed h tile
    __shared__ float b_s[2][KT2][BPITCH];   // [k][ch*4+gate] interleaved Wh tile

    const float* __restrict__ hin  = g_h[t & 1];
    float* __restrict__       hout = g_h[(t + 1) & 1];

    const int tid  = threadIdx.x;
    const int m0   = blockIdx.x << 5;       // batch tile base
    const int ch0  = blockIdx.y << 5;       // channel tile base
    const int w    = tid >> 5;
    const int lane = tid & 31;
    const int mg   = lane >> 4;              // 0/1 m-subgroup
    const int chl  = lane & 15;              // channel within half
    const int mb   = (w & 3) * 8 + mg * 4;   // local m base: 4 rows mb..mb+3
    const int chL  = (w >> 2) * 16 + chl;    // local channel 0..31
    const int ch   = ch0 + chL;

    // loader indices
    const int akm = tid & 31;                // a: m row
    const int aks = tid >> 5;                // a: k segment (4 floats)
    const int bkb = tid >> 3;                // b: k row
    const int bsg = tid & 7;                 // b: channel segment (4 ch)

    float2 acc[4][2];                        // [gate][m-pair]
#pragma unroll
    for (int q = 0; q < 4; ++q) {
        acc[q][0] = make_float2(0.f, 0.f);
        acc[q][1] = make_float2(0.f, 0.f);
    }

    float4 ra;
    float4 rb[4];

    auto loadA = [&](int k0) {
        ra = *(const float4*)&hin[(size_t)(m0 + akm) * HH + k0 + aks * 4];
    };
    auto loadB = [&](int k0) {
#pragma unroll
        for (int g = 0; g < 4; ++g)
            rb[g] = *(const float4*)&Wh[(size_t)(k0 + bkb) * G4 + g * HH + ch0 + bsg * 4];
    };
    auto stsA = [&](int buf) {
        a_s[buf][aks * 4 + 0][akm] = ra.x;
        a_s[buf][aks * 4 + 1][akm] = ra.y;
        a_s[buf][aks * 4 + 2][akm] = ra.z;
        a_s[buf][aks * 4 + 3][akm] = ra.w;
    };
    auto stsB = [&](int buf) {
        // 4x4 register transpose: dest [ch][gate] interleave
        float4 w0 = make_float4(rb[0].x, rb[1].x, rb[2].x, rb[3].x);
        float4 w1 = make_float4(rb[0].y, rb[1].y, rb[2].y, rb[3].y);
        float4 w2 = make_float4(rb[0].z, rb[1].z, rb[2].z, rb[3].z);
        float4 w3 = make_float4(rb[0].w, rb[1].w, rb[2].w, rb[3].w);
        *(float4*)&b_s[buf][bkb][(bsg * 4 + 0) * 4] = w0;
        *(float4*)&b_s[buf][bkb][(bsg * 4 + 1) * 4] = w1;
        *(float4*)&b_s[buf][bkb][(bsg * 4 + 2) * 4] = w2;
        *(float4*)&b_s[buf][bkb][(bsg * 4 + 3) * 4] = w3;
    };

    const int NS = HH / KT2;   // 16 stages
    loadA(0); loadB(0);
    stsA(0); stsB(0);
    __syncthreads();

    for (int s = 0; s < NS; ++s) {
        const int buf = s & 1;
        if (s + 1 < NS) { loadA((s + 1) * KT2); loadB((s + 1) * KT2); }
#pragma unroll
        for (int kk = 0; kk < KT2; ++kk) {
            float4 av = *(const float4*)&a_s[buf][kk][mb];
            float4 bq = *(const float4*)&b_s[buf][kk][chL * 4];
            float2 a01 = make_float2(av.x, av.y);
            float2 a23 = make_float2(av.z, av.w);
            float2 d;
            d = make_float2(bq.x, bq.x);
            acc[0][0] = ffma2(a01, d, acc[0][0]);
            acc[0][1] = ffma2(a23, d, acc[0][1]);
            d = make_float2(bq.y, bq.y);
            acc[1][0] = ffma2(a01, d, acc[1][0]);
            acc[1][1] = ffma2(a23, d, acc[1][1]);
            d = make_float2(bq.z, bq.z);
            acc[2][0] = ffma2(a01, d, acc[2][0]);
            acc[2][1] = ffma2(a23, d, acc[2][1]);
            d = make_float2(bq.w, bq.w);
            acc[3][0] = ffma2(a01, d, acc[3][0]);
            acc[3][1] = ffma2(a23, d, acc[3][1]);
        }
        if (s + 1 < NS) { stsA(buf ^ 1); stsB(buf ^ 1); }
        __syncthreads();
    }

    // fused epilogue: gate nonlinearities + phased time gate + state update
    const float tv = tau[ch];
    const float sv = shift[ch];
    float xph = ((float)t - sv) / tv;
    float phi = xph - floorf(xph);
    float kg = (phi < 0.025f) ? (40.0f * phi)
             : (phi < 0.05f)  ? (2.0f - 40.0f * phi)
                              : (0.001f * phi);

    const size_t xwbase = (size_t)t * BB * G4;
#pragma unroll
    for (int p = 0; p < 2; ++p) {
#pragma unroll
        for (int r = 0; r < 2; ++r) {
            int m = m0 + mb + 2 * p + r;
            size_t xo = xwbase + (size_t)m * G4 + ch;
            float gi = (r ? acc[0][p].y : acc[0][p].x) + g_xw[xo];
            float gf = (r ? acc[1][p].y : acc[1][p].x) + g_xw[xo + 512];
            float gg = (r ? acc[2][p].y : acc[2][p].x) + g_xw[xo + 1024];
            float go = (r ? acc[3][p].y : acc[3][p].x) + g_xw[xo + 1536];
            gi = 1.0f / (1.0f + __expf(-gi));
            gf = 1.0f / (1.0f + __expf(-gf));
            gg = tanhf(gg);
            go = 1.0f / (1.0f + __expf(-go));
            size_t so = (size_t)m * HH + ch;
            float cold = g_c[so];
            float ct = gf * cold + gi * gg;
            float ht = go * tanhf(ct);
            float hold = hin[so];
            g_c[so]  = kg * ct + (1.0f - kg) * cold;
            hout[so] = kg * ht + (1.0f - kg) * hold;
        }
    }
}

// ---------------------------------------------------------------------------
// Phase 3: logits = hT @ fc_w + fc_b; log_softmax over C=60.
// ---------------------------------------------------------------------------
__global__ void head_kernel(const float* __restrict__ fc_w,
                            const float* __restrict__ fc_b,
                            float* __restrict__ out) {
    __shared__ float hrow[HH];
    __shared__ float logits[CC];
    __shared__ float s_lse;
    const int b = blockIdx.x;
    const int tid = threadIdx.x;   // 64 threads

    for (int i = tid; i < HH; i += 64) hrow[i] = g_h[0][(size_t)b * HH + i];
    __syncthreads();

    if (tid < CC) {
        float s = fc_b[tid];
#pragma unroll 8
        for (int k = 0; k < HH; ++k) s += hrow[k] * fc_w[(size_t)k * CC + tid];
        logits[tid] = s;
    }
    __syncthreads();

    if (tid == 0) {
        float mx = -1e30f;
        for (int i = 0; i < CC; ++i) mx = fmaxf(mx, logits[i]);
        float sm = 0.0f;
        for (int i = 0; i < CC; ++i) sm += expf(logits[i] - mx);
        s_lse = mx + logf(sm);
    }
    __syncthreads();

    if (tid < CC) out[(size_t)b * CC + tid] = logits[tid] - s_lse;
}

// ---------------------------------------------------------------------------
// Launch
// ---------------------------------------------------------------------------
extern "C" void kernel_launch(void* const* d_in, const int* in_sizes, int n_in,
                              void* d_out, int out_size) {
    const float* x     = (const float*)d_in[0];
    const float* Wx    = (const float*)d_in[1];
    const float* Wh    = (const float*)d_in[2];
    const float* bias  = (const float*)d_in[3];
    const float* tau   = (const float*)d_in[4];
    const float* shift = (const float*)d_in[5];
    const float* fc_w  = (const float*)d_in[6];
    const float* fc_b  = (const float*)d_in[7];
    float* out = (float*)d_out;

    zero_state<<<(BB * HH + 255) / 256, 256>>>();

    dim3 g1(G4 / 128, (TT * BB) / 128);   // (16, 512)
    xw_gemm<<<g1, 256>>>(x, Wx, bias);

    dim3 g2(BB / 32, HH / 32);            // (8, 16)
    for (int t = 0; t < TT; ++t)
        lstm_step<<<g2, 256>>>(Wh, tau, shift, t);

    head_kernel<<<BB, 64>>>(fc_w, fc_b, out);
}